// round 9
// baseline (speedup 1.0000x reference)
#include <cuda_runtime.h>
#include <cuda_fp16.h>
#include <cstdint>

// hashNerf on sm_103 (plain target), R9.
// K1: hash encode with smem-cached v1/v2 corner tables (+inline weight prep).
// K2: MLP via mma.sync m16n8k16 HMMA, TILES=8 point-tiles per CTA.

#define LVL   16
#define TSZ   262144
#define TMASK 0x3FFFFu
#define N_PTS_MAX 1048576
#define TILES 8
#define N_TAB {16.f,21.f,27.f,36.f,48.f,64.f,84.f,111.f,147.f,194.f,256.f,337.f,445.f,588.f,776.f,1024.f}

#define WPAD 72          // weight row stride in halves (144B -> conflict-free ldmatrix)
#define FPAD 40          // feature row stride in halves (80B, 16B-aligned rows)
#define OFF_W1 0
#define OFF_W2 2304      // 32*72
#define OFF_W3 6912      // 2304 + 64*72
#define OFF_W4 11520     // 6912 + 64*72
#define IMG_HALVES 12032 // + 64*8
#define PREP_BLOCKS 47   // ceil(12032/256)

// v2/v1 smem cache geometry (counts = N_l + 1)
#define SV2_TOT 4190
#define SV1_TOT 758
#define SV1_LVLS 10

__device__ __align__(16) unsigned short g_prepW[IMG_HALVES];
__device__ uint4 g_feat[N_PTS_MAX * 4];   // 32 f16 per point = 4 uint4

// ---------- helpers ----------
__device__ __forceinline__ uint32_t smem_u32(const void* p) {
    uint32_t a;
    asm("{ .reg .u64 t; cvta.to.shared.u64 t, %1; cvt.u32.u64 %0, t; }" : "=r"(a) : "l"(p));
    return a;
}
__device__ __forceinline__ uint32_t pack_h2(float lo, float hi) {
    uint32_t r;
    asm("cvt.rn.f16x2.f32 %0, %1, %2;" : "=r"(r) : "f"(hi), "f"(lo));
    return r;
}
__device__ __forceinline__ void ldsm_x4(uint32_t& r0, uint32_t& r1, uint32_t& r2, uint32_t& r3, uint32_t addr) {
    asm volatile("ldmatrix.sync.aligned.m8n8.x4.shared.b16 {%0,%1,%2,%3}, [%4];"
                 : "=r"(r0), "=r"(r1), "=r"(r2), "=r"(r3) : "r"(addr));
}
__device__ __forceinline__ void ldsm_x4_t(uint32_t& r0, uint32_t& r1, uint32_t& r2, uint32_t& r3, uint32_t addr) {
    asm volatile("ldmatrix.sync.aligned.m8n8.x4.trans.shared.b16 {%0,%1,%2,%3}, [%4];"
                 : "=r"(r0), "=r"(r1), "=r"(r2), "=r"(r3) : "r"(addr));
}
__device__ __forceinline__ void ldsm_x2_t(uint32_t& r0, uint32_t& r1, uint32_t addr) {
    asm volatile("ldmatrix.sync.aligned.m8n8.x2.trans.shared.b16 {%0,%1}, [%2];"
                 : "=r"(r0), "=r"(r1) : "r"(addr));
}
__device__ __forceinline__ void mma16816(float* c, const uint32_t* a, uint32_t b0, uint32_t b1) {
    asm volatile("mma.sync.aligned.m16n8k16.row.col.f32.f16.f16.f32 "
                 "{%0,%1,%2,%3}, {%4,%5,%6,%7}, {%8,%9}, {%0,%1,%2,%3};"
                 : "+f"(c[0]), "+f"(c[1]), "+f"(c[2]), "+f"(c[3])
                 : "r"(a[0]), "r"(a[1]), "r"(a[2]), "r"(a[3]), "r"(b0), "r"(b1));
}
__device__ __forceinline__ float lrelu(float v) { return (v >= 0.f) ? v : 0.01f * v; }

// ---------- K1: hash encode (+ inline weight prep on first blocks) ----------
__global__ void __launch_bounds__(256)
encode_kernel(const float* __restrict__ X, const float* __restrict__ tab,
              const float* __restrict__ W1, const float* __restrict__ W2,
              const float* __restrict__ W3, const float* __restrict__ W4, int n) {
    __shared__ float2 sV2[SV2_TOT];   // level-prefix entries (v2 & v0 corners)
    __shared__ float2 sV1[SV1_TOT];   // hash(yi) entries, levels 0..9 (v1 corner)

    const int tid = threadIdx.x;

    // inline weight prep (one chunk per early block; MLP launches later)
    if (blockIdx.x < PREP_BLOCKS) {
        int idx = blockIdx.x * 256 + tid;
        if (idx < IMG_HALVES) {
            float v = 0.f;
            if (idx < OFF_W2) {
                int k = idx / WPAD, c = idx % WPAD;
                if (c < 64) v = W1[k * 64 + c];
            } else if (idx < OFF_W3) {
                int j = idx - OFF_W2, k = j / WPAD, c = j % WPAD;
                if (c < 64) v = W2[k * 64 + c];
            } else if (idx < OFF_W4) {
                int j = idx - OFF_W3, k = j / WPAD, c = j % WPAD;
                if (c < 64) v = W3[k * 64 + c];
            } else {
                int j = idx - OFF_W4, k = j >> 3, c = j & 7;
                if (c < 3) v = W4[k * 3 + c];
            }
            unsigned short hv;
            asm("{ .reg .b16 t; cvt.rn.f16.f32 t, %1; mov.b16 %0, t; }" : "=h"(hv) : "f"(v));
            g_prepW[idx] = hv;
        }
    }

    const int cnt[16]  = {17,22,28,37,49,65,85,112,148,195,257,338,446,589,777,1025};
    const int off2[16] = {0,17,39,67,104,153,218,303,415,563,758,1015,1353,1799,2388,3165};
    const int off1[10] = {0,17,39,67,104,153,218,303,415,563};

    // prefill caches
#pragma unroll 1
    for (int l = 0; l < LVL; l++) {
        const float2* tl = (const float2*)tab + (size_t)l * TSZ;
        for (int i = tid; i < cnt[l]; i += 256) sV2[off2[l] + i] = __ldg(tl + i);
    }
#pragma unroll 1
    for (int l = 0; l < SV1_LVLS; l++) {
        const float2* tl = (const float2*)tab + (size_t)l * TSZ;
        for (int i = tid; i < cnt[l]; i += 256)
            sV1[off1[l] + i] = __ldg(tl + (((unsigned)i * 2654435761u) & TMASK));
    }
    __syncthreads();

    const int pt = blockIdx.x * 256 + tid;
    if (pt >= n) return;
    const float Ntab[16] = N_TAB;
    const float2 xy = __ldg((const float2*)X + pt);
    const float x = xy.x, y = xy.y;

    uint32_t packed[16];
#pragma unroll
    for (int l = 0; l < LVL; l++) {
        float xs = x * Ntab[l], ys = y * Ntab[l];
        float xf = floorf(xs), yf = floorf(ys);
        unsigned xi = (unsigned)xf, yi = (unsigned)yf;
        unsigned hy = (yi * 2654435761u) & TMASK;
        unsigned hxy = xi ^ hy;
        const float2* tl = (const float2*)tab + (size_t)l * TSZ;
        float2 v0 = sV2[off2[l]];
        float2 v2 = sV2[off2[l] + xi];
        float2 v1 = (l < SV1_LVLS) ? sV1[off1[l] + yi] : __ldg(tl + hy);
        float2 v3 = __ldg(tl + hxy);
        float fx = xs - xf, fy = ys - yf;
        float cx = 1.f - fx, cy = 1.f - fy;
        float w0 = cx * cy, w1 = cx * fy, w2 = fx * cy, w3 = fx * fy;
        float f0 = w0 * v0.x + w1 * v1.x + w2 * v2.x + w3 * v3.x;
        float f1 = w0 * v0.y + w1 * v1.y + w2 * v2.y + w3 * v3.y;
        packed[l] = pack_h2(f0, f1);
    }
    uint4* dst = g_feat + (size_t)pt * 4;
#pragma unroll
    for (int i = 0; i < 4; i++)
        dst[i] = make_uint4(packed[4 * i], packed[4 * i + 1], packed[4 * i + 2], packed[4 * i + 3]);
}

// ---------- K2: MLP ----------
__global__ void __launch_bounds__(128)
mlp_kernel(const float* __restrict__ b1, const float* __restrict__ b2,
           const float* __restrict__ b3, const float* __restrict__ b4,
           float* __restrict__ out, int n) {
    __shared__ __align__(16) unsigned short sW[IMG_HALVES];      // 24064 B
    __shared__ __align__(16) unsigned short sF[4][32 * FPAD];    // 10240 B
    __shared__ float sb[3][64];
    __shared__ float sb4[8];

    const int tid  = threadIdx.x;
    const int warp = tid >> 5;
    const int lane = tid & 31;

    {
        const uint4* src = (const uint4*)g_prepW;
        uint4* dst = (uint4*)sW;
        for (int i = tid; i < IMG_HALVES / 8; i += 128) dst[i] = src[i];
    }
    if (tid < 64) { sb[0][tid] = b1[tid]; sb[1][tid] = b2[tid]; sb[2][tid] = b3[tid]; }
    if (tid < 8) sb4[tid] = (tid < 3) ? b4[tid] : 0.f;
    __syncthreads();

    const uint32_t uW = smem_u32(sW);
    const uint32_t uF = smem_u32(sF[warp]);
    const int l15 = lane & 15;
    const int lhi = (lane >> 4) << 3;       // +8 halves for upper half-warp
    const int tg2 = (lane & 3) << 1;        // accumulator column pair base
    const int g   = lane >> 2;              // accumulator row base

#pragma unroll 1
    for (int it = 0; it < TILES; it++) {
        const int pbase = (blockIdx.x * TILES + it) * 128 + warp * 32;
        if (pbase >= n) break;

        // stage this warp's 32 feature rows (coalesced uint4 copy into FPAD rows)
        __syncwarp();   // it>0: prior ldsm reads complete before overwrite
        {
            const uint4* src = g_feat + (size_t)pbase * 4;   // 128 uint4
            unsigned short* dstbase = sF[warp];
#pragma unroll
            for (int i = 0; i < 4; i++) {
                int j = lane + 32 * i;                        // 0..127
                uint4 v = src[j];                             // point j>>2, slot j&3
                *(uint4*)(dstbase + (j >> 2) * FPAD + (j & 3) * 8) = v;
            }
        }
        __syncwarp();

        // A fragments: a[mtile][ktile][4]
        uint32_t a[2][4][4];
#pragma unroll
        for (int mt = 0; mt < 2; mt++)
#pragma unroll
            for (int kt = 0; kt < 2; kt++) {
                uint32_t ad = uF + (uint32_t)(((mt * 16 + l15) * FPAD + kt * 16 + lhi) * 2);
                ldsm_x4(a[mt][kt][0], a[mt][kt][1], a[mt][kt][2], a[mt][kt][3], ad);
            }

        const uint32_t woffs[3] = {OFF_W1 * 2u, OFF_W2 * 2u, OFF_W3 * 2u};
        const int nkts[3] = {2, 4, 4};

#pragma unroll 1
        for (int layer = 0; layer < 3; layer++) {
            const uint32_t wb = uW + woffs[layer];
            const int nkt = nkts[layer];
            float c[2][8][4];
#pragma unroll
            for (int mt = 0; mt < 2; mt++)
#pragma unroll
                for (int nt = 0; nt < 8; nt++) {
                    float v0 = sb[layer][8 * nt + tg2];
                    float v1 = sb[layer][8 * nt + tg2 + 1];
                    c[mt][nt][0] = v0; c[mt][nt][1] = v1;
                    c[mt][nt][2] = v0; c[mt][nt][3] = v1;
                }
#pragma unroll
            for (int kt = 0; kt < 4; kt++) {
                if (kt >= nkt) break;
#pragma unroll
                for (int n2 = 0; n2 < 4; n2++) {
                    uint32_t b0, b1, b2, b3;
                    uint32_t bd = wb + (uint32_t)(((kt * 16 + l15) * WPAD + n2 * 16 + lhi) * 2);
                    ldsm_x4_t(b0, b1, b2, b3, bd);
#pragma unroll
                    for (int mt = 0; mt < 2; mt++) {
                        mma16816(c[mt][2 * n2],     a[mt][kt], b0, b1);
                        mma16816(c[mt][2 * n2 + 1], a[mt][kt], b2, b3);
                    }
                }
            }
            // leaky-relu + repack accumulators as next-layer A fragments
#pragma unroll
            for (int mt = 0; mt < 2; mt++)
#pragma unroll
                for (int j = 0; j < 4; j++) {
                    a[mt][j][0] = pack_h2(lrelu(c[mt][2 * j][0]),     lrelu(c[mt][2 * j][1]));
                    a[mt][j][1] = pack_h2(lrelu(c[mt][2 * j][2]),     lrelu(c[mt][2 * j][3]));
                    a[mt][j][2] = pack_h2(lrelu(c[mt][2 * j + 1][0]), lrelu(c[mt][2 * j + 1][1]));
                    a[mt][j][3] = pack_h2(lrelu(c[mt][2 * j + 1][2]), lrelu(c[mt][2 * j + 1][3]));
                }
        }

        // ---- layer 4: 64 -> 3 (single n8 tile, cols 3..7 zero-padded) ----
        float c4[2][4];
#pragma unroll
        for (int mt = 0; mt < 2; mt++) {
            c4[mt][0] = sb4[tg2]; c4[mt][1] = sb4[tg2 + 1];
            c4[mt][2] = sb4[tg2]; c4[mt][3] = sb4[tg2 + 1];
        }
#pragma unroll
        for (int kt = 0; kt < 4; kt++) {
            uint32_t b0, b1;
            uint32_t bd = uW + OFF_W4 * 2u + (uint32_t)(((kt * 16 + l15) * 8) * 2);
            ldsm_x2_t(b0, b1, bd);
#pragma unroll
            for (int mt = 0; mt < 2; mt++) mma16816(c4[mt], a[mt][kt], b0, b1);
        }

        // relu + predicated stores: rows (g, g+8) per m-tile, cols (tg2, tg2+1)
#pragma unroll
        for (int mt = 0; mt < 2; mt++) {
            int p0 = pbase + mt * 16 + g;
            int p1 = p0 + 8;
            float v0 = fmaxf(c4[mt][0], 0.f), v1 = fmaxf(c4[mt][1], 0.f);
            float v2 = fmaxf(c4[mt][2], 0.f), v3 = fmaxf(c4[mt][3], 0.f);
            if (tg2 < 3) {
                if (p0 < n) out[3 * p0 + tg2] = v0;
                if (p1 < n) out[3 * p1 + tg2] = v2;
            }
            if (tg2 + 1 < 3) {
                if (p0 < n) out[3 * p0 + tg2 + 1] = v1;
                if (p1 < n) out[3 * p1 + tg2 + 1] = v3;
            }
        }
    }
}

extern "C" void kernel_launch(void* const* d_in, const int* in_sizes, int n_in,
                              void* d_out, int out_size) {
    const float* X   = (const float*)d_in[0];
    const float* tab = (const float*)d_in[1];
    const float* W1  = (const float*)d_in[2];
    const float* b1  = (const float*)d_in[3];
    const float* W2  = (const float*)d_in[4];
    const float* b2  = (const float*)d_in[5];
    const float* W3  = (const float*)d_in[6];
    const float* b3  = (const float*)d_in[7];
    const float* W4  = (const float*)d_in[8];
    const float* b4  = (const float*)d_in[9];
    float* out = (float*)d_out;

    int n = in_sizes[0] / 2;
    encode_kernel<<<(n + 255) / 256, 256>>>(X, tab, W1, W2, W3, W4, n);
    int ptile = 128 * TILES;
    mlp_kernel<<<(n + ptile - 1) / ptile, 128>>>(b1, b2, b3, b4, out, n);
}

// round 10
// speedup vs baseline: 1.7979x; 1.7979x over previous
#include <cuda_runtime.h>
#include <cuda_fp16.h>
#include <cstdint>

// hashNerf on sm_103 (plain target), R10.
// K1: hash encode, direct __ldg gathers (R8 form) + inline weight prep.
// K2: MLP via mma.sync m16n8k16 HMMA, TILES=4, launch_bounds(128,4) for 16 warps/SM.

#define LVL   16
#define TSZ   262144
#define TMASK 0x3FFFFu
#define N_PTS_MAX 1048576
#define TILES 4
#define N_TAB {16.f,21.f,27.f,36.f,48.f,64.f,84.f,111.f,147.f,194.f,256.f,337.f,445.f,588.f,776.f,1024.f}

#define WPAD 72          // weight row stride in halves (144B -> conflict-free ldmatrix)
#define FPAD 40          // feature row stride in halves (80B, 16B-aligned rows)
#define OFF_W1 0
#define OFF_W2 2304      // 32*72
#define OFF_W3 6912      // 2304 + 64*72
#define OFF_W4 11520     // 6912 + 64*72
#define IMG_HALVES 12032 // + 64*8
#define PREP_BLOCKS 47   // ceil(12032/256)

__device__ __align__(16) unsigned short g_prepW[IMG_HALVES];
__device__ uint4 g_feat[N_PTS_MAX * 4];   // 32 f16 per point = 4 uint4

// ---------- helpers ----------
__device__ __forceinline__ uint32_t smem_u32(const void* p) {
    uint32_t a;
    asm("{ .reg .u64 t; cvta.to.shared.u64 t, %1; cvt.u32.u64 %0, t; }" : "=r"(a) : "l"(p));
    return a;
}
__device__ __forceinline__ uint32_t pack_h2(float lo, float hi) {
    uint32_t r;
    asm("cvt.rn.f16x2.f32 %0, %1, %2;" : "=r"(r) : "f"(hi), "f"(lo));
    return r;
}
__device__ __forceinline__ void ldsm_x4(uint32_t& r0, uint32_t& r1, uint32_t& r2, uint32_t& r3, uint32_t addr) {
    asm volatile("ldmatrix.sync.aligned.m8n8.x4.shared.b16 {%0,%1,%2,%3}, [%4];"
                 : "=r"(r0), "=r"(r1), "=r"(r2), "=r"(r3) : "r"(addr));
}
__device__ __forceinline__ void ldsm_x4_t(uint32_t& r0, uint32_t& r1, uint32_t& r2, uint32_t& r3, uint32_t addr) {
    asm volatile("ldmatrix.sync.aligned.m8n8.x4.trans.shared.b16 {%0,%1,%2,%3}, [%4];"
                 : "=r"(r0), "=r"(r1), "=r"(r2), "=r"(r3) : "r"(addr));
}
__device__ __forceinline__ void ldsm_x2_t(uint32_t& r0, uint32_t& r1, uint32_t addr) {
    asm volatile("ldmatrix.sync.aligned.m8n8.x2.trans.shared.b16 {%0,%1}, [%2];"
                 : "=r"(r0), "=r"(r1) : "r"(addr));
}
__device__ __forceinline__ void mma16816(float* c, const uint32_t* a, uint32_t b0, uint32_t b1) {
    asm volatile("mma.sync.aligned.m16n8k16.row.col.f32.f16.f16.f32 "
                 "{%0,%1,%2,%3}, {%4,%5,%6,%7}, {%8,%9}, {%0,%1,%2,%3};"
                 : "+f"(c[0]), "+f"(c[1]), "+f"(c[2]), "+f"(c[3])
                 : "r"(a[0]), "r"(a[1]), "r"(a[2]), "r"(a[3]), "r"(b0), "r"(b1));
}
__device__ __forceinline__ float lrelu(float v) { return (v >= 0.f) ? v : 0.01f * v; }

// ---------- K1: hash encode (+ inline weight prep on first 47 blocks) ----------
__global__ void __launch_bounds__(256)
encode_kernel(const float* __restrict__ X, const float* __restrict__ tab,
              const float* __restrict__ W1, const float* __restrict__ W2,
              const float* __restrict__ W3, const float* __restrict__ W4, int n) {
    const int tid = threadIdx.x;

    // inline weight prep (runs on early blocks; MLP kernel launches afterwards)
    if (blockIdx.x < PREP_BLOCKS) {
        int idx = blockIdx.x * 256 + tid;
        if (idx < IMG_HALVES) {
            float v = 0.f;
            if (idx < OFF_W2) {
                int k = idx / WPAD, c = idx % WPAD;
                if (c < 64) v = W1[k * 64 + c];
            } else if (idx < OFF_W3) {
                int j = idx - OFF_W2, k = j / WPAD, c = j % WPAD;
                if (c < 64) v = W2[k * 64 + c];
            } else if (idx < OFF_W4) {
                int j = idx - OFF_W3, k = j / WPAD, c = j % WPAD;
                if (c < 64) v = W3[k * 64 + c];
            } else {
                int j = idx - OFF_W4, k = j >> 3, c = j & 7;
                if (c < 3) v = W4[k * 3 + c];
            }
            unsigned short hv;
            asm("{ .reg .b16 t; cvt.rn.f16.f32 t, %1; mov.b16 %0, t; }" : "=h"(hv) : "f"(v));
            g_prepW[idx] = hv;
        }
    }

    const int pt = blockIdx.x * 256 + tid;
    if (pt >= n) return;
    const float Ntab[16] = N_TAB;
    const float2 xy = __ldg((const float2*)X + pt);
    const float x = xy.x, y = xy.y;

    uint32_t packed[16];
#pragma unroll
    for (int l = 0; l < LVL; l++) {
        float xs = x * Ntab[l], ys = y * Ntab[l];
        float xf = floorf(xs), yf = floorf(ys);
        unsigned xi = (unsigned)xf, yi = (unsigned)yf;
        unsigned hy = (yi * 2654435761u) & TMASK;
        unsigned hx = xi;                 // < 2^18 already
        unsigned hxy = hx ^ hy;
        const float2* tl = (const float2*)tab + (size_t)l * TSZ;
        float2 v0 = __ldg(tl);
        float2 v1 = __ldg(tl + hy);
        float2 v2 = __ldg(tl + hx);
        float2 v3 = __ldg(tl + hxy);
        float fx = xs - xf, fy = ys - yf;
        float cx = 1.f - fx, cy = 1.f - fy;
        float w0 = cx * cy, w1 = cx * fy, w2 = fx * cy, w3 = fx * fy;
        float f0 = w0 * v0.x + w1 * v1.x + w2 * v2.x + w3 * v3.x;
        float f1 = w0 * v0.y + w1 * v1.y + w2 * v2.y + w3 * v3.y;
        packed[l] = pack_h2(f0, f1);
    }
    uint4* dst = g_feat + (size_t)pt * 4;
#pragma unroll
    for (int i = 0; i < 4; i++)
        dst[i] = make_uint4(packed[4 * i], packed[4 * i + 1], packed[4 * i + 2], packed[4 * i + 3]);
}

// ---------- K2: MLP ----------
__global__ void __launch_bounds__(128, 4)
mlp_kernel(const float* __restrict__ b1, const float* __restrict__ b2,
           const float* __restrict__ b3, const float* __restrict__ b4,
           float* __restrict__ out, int n) {
    __shared__ __align__(16) unsigned short sW[IMG_HALVES];      // 24064 B
    __shared__ __align__(16) unsigned short sF[4][32 * FPAD];    // 10240 B
    __shared__ float sb[3][64];
    __shared__ float sb4[8];

    const int tid  = threadIdx.x;
    const int warp = tid >> 5;
    const int lane = tid & 31;

    {
        const uint4* src = (const uint4*)g_prepW;
        uint4* dst = (uint4*)sW;
        for (int i = tid; i < IMG_HALVES / 8; i += 128) dst[i] = src[i];
    }
    if (tid < 64) { sb[0][tid] = b1[tid]; sb[1][tid] = b2[tid]; sb[2][tid] = b3[tid]; }
    if (tid < 8) sb4[tid] = (tid < 3) ? b4[tid] : 0.f;
    __syncthreads();

    const uint32_t uW = smem_u32(sW);
    const uint32_t uF = smem_u32(sF[warp]);
    const int l15 = lane & 15;
    const int lhi = (lane >> 4) << 3;       // +8 halves for upper half-warp
    const int tg2 = (lane & 3) << 1;        // accumulator column pair base
    const int g   = lane >> 2;              // accumulator row base

#pragma unroll 1
    for (int it = 0; it < TILES; it++) {
        const int pbase = (blockIdx.x * TILES + it) * 128 + warp * 32;
        if (pbase >= n) break;

        // stage this warp's 32 feature rows (coalesced uint4 copy into FPAD rows)
        __syncwarp();   // it>0: prior ldsm reads complete before overwrite
        {
            const uint4* src = g_feat + (size_t)pbase * 4;   // 128 uint4
            unsigned short* dstbase = sF[warp];
#pragma unroll
            for (int i = 0; i < 4; i++) {
                int j = lane + 32 * i;                        // 0..127
                uint4 v = src[j];                             // point j>>2, slot j&3
                *(uint4*)(dstbase + (j >> 2) * FPAD + (j & 3) * 8) = v;
            }
        }
        __syncwarp();

        // A fragments: a[mtile][ktile][4]
        uint32_t a[2][4][4];
#pragma unroll
        for (int mt = 0; mt < 2; mt++)
#pragma unroll
            for (int kt = 0; kt < 2; kt++) {
                uint32_t ad = uF + (uint32_t)(((mt * 16 + l15) * FPAD + kt * 16 + lhi) * 2);
                ldsm_x4(a[mt][kt][0], a[mt][kt][1], a[mt][kt][2], a[mt][kt][3], ad);
            }

        const uint32_t woffs[3] = {OFF_W1 * 2u, OFF_W2 * 2u, OFF_W3 * 2u};
        const int nkts[3] = {2, 4, 4};

#pragma unroll 1
        for (int layer = 0; layer < 3; layer++) {
            const uint32_t wb = uW + woffs[layer];
            const int nkt = nkts[layer];
            float c[2][8][4];
#pragma unroll
            for (int mt = 0; mt < 2; mt++)
#pragma unroll
                for (int nt = 0; nt < 8; nt++) {
                    float v0 = sb[layer][8 * nt + tg2];
                    float v1 = sb[layer][8 * nt + tg2 + 1];
                    c[mt][nt][0] = v0; c[mt][nt][1] = v1;
                    c[mt][nt][2] = v0; c[mt][nt][3] = v1;
                }
#pragma unroll
            for (int kt = 0; kt < 4; kt++) {
                if (kt >= nkt) break;
#pragma unroll
                for (int n2 = 0; n2 < 4; n2++) {
                    uint32_t b0, b1, b2, b3;
                    uint32_t bd = wb + (uint32_t)(((kt * 16 + l15) * WPAD + n2 * 16 + lhi) * 2);
                    ldsm_x4_t(b0, b1, b2, b3, bd);
#pragma unroll
                    for (int mt = 0; mt < 2; mt++) {
                        mma16816(c[mt][2 * n2],     a[mt][kt], b0, b1);
                        mma16816(c[mt][2 * n2 + 1], a[mt][kt], b2, b3);
                    }
                }
            }
            // leaky-relu + repack accumulators as next-layer A fragments
#pragma unroll
            for (int mt = 0; mt < 2; mt++)
#pragma unroll
                for (int j = 0; j < 4; j++) {
                    a[mt][j][0] = pack_h2(lrelu(c[mt][2 * j][0]),     lrelu(c[mt][2 * j][1]));
                    a[mt][j][1] = pack_h2(lrelu(c[mt][2 * j][2]),     lrelu(c[mt][2 * j][3]));
                    a[mt][j][2] = pack_h2(lrelu(c[mt][2 * j + 1][0]), lrelu(c[mt][2 * j + 1][1]));
                    a[mt][j][3] = pack_h2(lrelu(c[mt][2 * j + 1][2]), lrelu(c[mt][2 * j + 1][3]));
                }
        }

        // ---- layer 4: 64 -> 3 (single n8 tile, cols 3..7 zero-padded) ----
        float c4[2][4];
#pragma unroll
        for (int mt = 0; mt < 2; mt++) {
            c4[mt][0] = sb4[tg2]; c4[mt][1] = sb4[tg2 + 1];
            c4[mt][2] = sb4[tg2]; c4[mt][3] = sb4[tg2 + 1];
        }
#pragma unroll
        for (int kt = 0; kt < 4; kt++) {
            uint32_t b0, b1;
            uint32_t bd = uW + OFF_W4 * 2u + (uint32_t)(((kt * 16 + l15) * 8) * 2);
            ldsm_x2_t(b0, b1, bd);
#pragma unroll
            for (int mt = 0; mt < 2; mt++) mma16816(c4[mt], a[mt][kt], b0, b1);
        }

        // relu + predicated stores: rows (g, g+8) per m-tile, cols (tg2, tg2+1)
#pragma unroll
        for (int mt = 0; mt < 2; mt++) {
            int p0 = pbase + mt * 16 + g;
            int p1 = p0 + 8;
            float v0 = fmaxf(c4[mt][0], 0.f), v1 = fmaxf(c4[mt][1], 0.f);
            float v2 = fmaxf(c4[mt][2], 0.f), v3 = fmaxf(c4[mt][3], 0.f);
            if (tg2 < 3) {
                if (p0 < n) out[3 * p0 + tg2] = v0;
                if (p1 < n) out[3 * p1 + tg2] = v2;
            }
            if (tg2 + 1 < 3) {
                if (p0 < n) out[3 * p0 + tg2 + 1] = v1;
                if (p1 < n) out[3 * p1 + tg2 + 1] = v3;
            }
        }
    }
}

extern "C" void kernel_launch(void* const* d_in, const int* in_sizes, int n_in,
                              void* d_out, int out_size) {
    const float* X   = (const float*)d_in[0];
    const float* tab = (const float*)d_in[1];
    const float* W1  = (const float*)d_in[2];
    const float* b1  = (const float*)d_in[3];
    const float* W2  = (const float*)d_in[4];
    const float* b2  = (const float*)d_in[5];
    const float* W3  = (const float*)d_in[6];
    const float* b3  = (const float*)d_in[7];
    const float* W4  = (const float*)d_in[8];
    const float* b4  = (const float*)d_in[9];
    float* out = (float*)d_out;

    int n = in_sizes[0] / 2;
    encode_kernel<<<(n + 255) / 256, 256>>>(X, tab, W1, W2, W3, W4, n);
    int ptile = 128 * TILES;
    mlp_kernel<<<(n + ptile - 1) / ptile, 128>>>(b1, b2, b3, b4, out, n);
}